// round 11
// baseline (speedup 1.0000x reference)
#include <cuda_runtime.h>
#include <cuda_bf16.h>

// MoE routing histogram, single fused kernel (float32 harness buffers).
//
// R11 vs R10: the real bottleneck was REGISTER-STARVED MLP -- launch_bounds(256)
// let 8 CTAs/SM co-reside, capping threads at 32 regs, so ptxas serialized the
// "MLP x4" loads. Fix: __launch_bounds__(256, 4) -> 64-reg budget, grid 592
// (4 CTAs/SM, one wave), and an 8-deep batch of independent int4 loads in the
// binade fast path (32 data regs in flight).
// Retained: dtype sniff, affine/LUT fallbacks, 8x per-warp replicated shared
// histograms, global-atomic partials, last-block finalize + scratch re-zero.

#define NB        592      // 148 SMs * 4 CTAs = one wave at 4 CTAs/SM
#define TPB       256
#define NWARPS    (TPB / 32)
#define MAX_BINS  256
#define BIN_PAD   (MAX_BINS + 1)
#define MAX_MAP   512

__device__ int g_counts[MAX_BINS];
__device__ unsigned g_done;

__global__ __launch_bounds__(TPB, 4) void hist_kernel(
    const int* __restrict__ ids, long long n,
    const int* __restrict__ emap, int map_n, int n_local,
    float* __restrict__ out, int out_elems)
{
    __shared__ int s_map[MAX_MAP];
    __shared__ int s_hist[NWARPS][BIN_PAD];
    __shared__ int s_ids_int_ok, s_map_int_ok, s_affine, s_off;

    const int tid = threadIdx.x;

    // ---- dtype sniff ----
    if (tid == 0) { s_ids_int_ok = 1; s_map_int_ok = 1; s_affine = 1; s_off = 0x7FFFFFFF; }
    __syncthreads();
    if (tid < 256 && (long long)tid < n) {
        if ((unsigned)ids[tid] >= 65536u) atomicAnd(&s_ids_int_ok, 0);
    }
    if (emap != nullptr && tid < map_n) {
        unsigned w = (unsigned)emap[tid];
        if (w >= 65536u && w != 0xFFFFFFFFu) atomicAnd(&s_map_int_ok, 0);
    }
    __syncthreads();
    const int ids_float = !s_ids_int_ok;
    const int map_float = !s_map_int_ok;

    // ---- build LUT in int space ----
    int eff_map_n = map_n;
    if (emap != nullptr && map_n > 0) {
        if (map_float) {
            const float* mf = (const float*)emap;
            for (int i = tid; i < map_n; i += TPB) {
                float v = mf[i];
                s_map[i] = (v >= 0.0f && v < (float)MAX_BINS) ? (int)v : -1;
            }
        } else {
            for (int i = tid; i < map_n; i += TPB) s_map[i] = emap[i];
        }
    } else {
        eff_map_n = MAX_MAP;
        for (int i = tid; i < MAX_MAP; i += TPB) s_map[i] = (i < n_local) ? i : -1;
    }
    for (int i = tid; i < NWARPS * BIN_PAD; i += TPB) (&s_hist[0][0])[i] = 0;
    __syncthreads();

    // ---- affine detection ----
    const unsigned un = (unsigned)n_local;
    for (int i = tid; i < eff_map_n; i += TPB)
        if (s_map[i] >= 0) atomicMin(&s_off, i - s_map[i]);
    __syncthreads();
    const int off = s_off;
    for (int i = tid; i < eff_map_n; i += TPB) {
        int expect = ((unsigned)(i - off) < un) ? (i - off) : -1;
        if (s_map[i] != expect) atomicAnd(&s_affine, 0);
    }
    __syncthreads();
    const int affine = s_affine && (off != 0x7FFFFFFF) && (off >= 0) &&
                       (off + (int)un <= eff_map_n);

    // ---- binade fast-path constants ----
    int binade = 0; unsigned base_bits = 0, span = 0; int sh = 0;
    if (affine && ids_float && off > 0 && (int)un > 0) {
        int e_lo = 31 - __clz(off);
        int e_hi = 31 - __clz(off + (int)un - 1);
        if (e_lo == e_hi && e_lo <= 23) {
            binade    = 1;
            sh        = 23 - e_lo;
            base_bits = __float_as_uint((float)off);
            span      = un << sh;
        }
    }

    int* hist = s_hist[tid >> 5];
    const unsigned um = (unsigned)eff_map_n;
    const float off_f = (float)off;
    const long long st = (long long)NB * TPB;

#define PROC_BIN(W)                                                     \
    {                                                                   \
        unsigned _d = (unsigned)(W) - base_bits;                        \
        if (_d < span) atomicAdd(&hist[_d >> sh], 1);                   \
    }
#define PROC_F_AFF(W)                                                   \
    {                                                                   \
        int _m = (int)(__int_as_float(W) - off_f);                      \
        if ((unsigned)_m < un) atomicAdd(&hist[_m], 1);                 \
    }
#define PROC_F_LUT(W)                                                   \
    {                                                                   \
        unsigned _idx = (unsigned)(int)__int_as_float(W);               \
        int _m = (_idx < um) ? s_map[_idx] : -1;                        \
        if ((unsigned)_m < un) atomicAdd(&hist[_m], 1);                 \
    }
#define PROC_I_AFF(W)                                                   \
    {                                                                   \
        int _m = (W) - off;                                             \
        if ((unsigned)_m < un) atomicAdd(&hist[_m], 1);                 \
    }
#define PROC_I_LUT(W)                                                   \
    {                                                                   \
        unsigned _idx = (unsigned)(W);                                  \
        int _m = (_idx < um) ? s_map[_idx] : -1;                        \
        if ((unsigned)_m < un) atomicAdd(&hist[_m], 1);                 \
    }

    const int4* __restrict__ v = (const int4*)ids;
    const long long n4 = n >> 2;
    long long i = (long long)blockIdx.x * TPB + tid;

    if (binade) {
        // 8 independent int4 loads in flight (needs the 64-reg budget).
        for (; i + 7 * st < n4; i += 8 * st) {
            int4 v0 = __ldg(&v[i]);
            int4 v1 = __ldg(&v[i + st]);
            int4 v2 = __ldg(&v[i + 2 * st]);
            int4 v3 = __ldg(&v[i + 3 * st]);
            int4 v4 = __ldg(&v[i + 4 * st]);
            int4 v5 = __ldg(&v[i + 5 * st]);
            int4 v6 = __ldg(&v[i + 6 * st]);
            int4 v7 = __ldg(&v[i + 7 * st]);
            PROC_BIN(v0.x); PROC_BIN(v0.y); PROC_BIN(v0.z); PROC_BIN(v0.w);
            PROC_BIN(v1.x); PROC_BIN(v1.y); PROC_BIN(v1.z); PROC_BIN(v1.w);
            PROC_BIN(v2.x); PROC_BIN(v2.y); PROC_BIN(v2.z); PROC_BIN(v2.w);
            PROC_BIN(v3.x); PROC_BIN(v3.y); PROC_BIN(v3.z); PROC_BIN(v3.w);
            PROC_BIN(v4.x); PROC_BIN(v4.y); PROC_BIN(v4.z); PROC_BIN(v4.w);
            PROC_BIN(v5.x); PROC_BIN(v5.y); PROC_BIN(v5.z); PROC_BIN(v5.w);
            PROC_BIN(v6.x); PROC_BIN(v6.y); PROC_BIN(v6.z); PROC_BIN(v6.w);
            PROC_BIN(v7.x); PROC_BIN(v7.y); PROC_BIN(v7.z); PROC_BIN(v7.w);
        }
        for (; i < n4; i += st) {
            int4 v0 = __ldg(&v[i]);
            PROC_BIN(v0.x); PROC_BIN(v0.y); PROC_BIN(v0.z); PROC_BIN(v0.w);
        }
        if (blockIdx.x == 0)
            for (long long j = (n4 << 2) + tid; j < n; j += TPB) PROC_BIN(ids[j]);
    } else if (ids_float && affine) {
        for (; i + st < n4; i += 2 * st) {
            int4 va = __ldg(&v[i]);
            int4 vb = __ldg(&v[i + st]);
            PROC_F_AFF(va.x); PROC_F_AFF(va.y); PROC_F_AFF(va.z); PROC_F_AFF(va.w);
            PROC_F_AFF(vb.x); PROC_F_AFF(vb.y); PROC_F_AFF(vb.z); PROC_F_AFF(vb.w);
        }
        for (; i < n4; i += st) {
            int4 va = __ldg(&v[i]);
            PROC_F_AFF(va.x); PROC_F_AFF(va.y); PROC_F_AFF(va.z); PROC_F_AFF(va.w);
        }
        if (blockIdx.x == 0)
            for (long long j = (n4 << 2) + tid; j < n; j += TPB) PROC_F_AFF(ids[j]);
    } else if (ids_float) {
        for (; i + st < n4; i += 2 * st) {
            int4 va = __ldg(&v[i]);
            int4 vb = __ldg(&v[i + st]);
            PROC_F_LUT(va.x); PROC_F_LUT(va.y); PROC_F_LUT(va.z); PROC_F_LUT(va.w);
            PROC_F_LUT(vb.x); PROC_F_LUT(vb.y); PROC_F_LUT(vb.z); PROC_F_LUT(vb.w);
        }
        for (; i < n4; i += st) {
            int4 va = __ldg(&v[i]);
            PROC_F_LUT(va.x); PROC_F_LUT(va.y); PROC_F_LUT(va.z); PROC_F_LUT(va.w);
        }
        if (blockIdx.x == 0)
            for (long long j = (n4 << 2) + tid; j < n; j += TPB) PROC_F_LUT(ids[j]);
    } else if (affine) {
        for (; i + st < n4; i += 2 * st) {
            int4 va = __ldg(&v[i]);
            int4 vb = __ldg(&v[i + st]);
            PROC_I_AFF(va.x); PROC_I_AFF(va.y); PROC_I_AFF(va.z); PROC_I_AFF(va.w);
            PROC_I_AFF(vb.x); PROC_I_AFF(vb.y); PROC_I_AFF(vb.z); PROC_I_AFF(vb.w);
        }
        for (; i < n4; i += st) {
            int4 va = __ldg(&v[i]);
            PROC_I_AFF(va.x); PROC_I_AFF(va.y); PROC_I_AFF(va.z); PROC_I_AFF(va.w);
        }
        if (blockIdx.x == 0)
            for (long long j = (n4 << 2) + tid; j < n; j += TPB) PROC_I_AFF(ids[j]);
    } else {
        for (; i + st < n4; i += 2 * st) {
            int4 va = __ldg(&v[i]);
            int4 vb = __ldg(&v[i + st]);
            PROC_I_LUT(va.x); PROC_I_LUT(va.y); PROC_I_LUT(va.z); PROC_I_LUT(va.w);
            PROC_I_LUT(vb.x); PROC_I_LUT(vb.y); PROC_I_LUT(vb.z); PROC_I_LUT(vb.w);
        }
        for (; i < n4; i += st) {
            int4 va = __ldg(&v[i]);
            PROC_I_LUT(va.x); PROC_I_LUT(va.y); PROC_I_LUT(va.z); PROC_I_LUT(va.w);
        }
        if (blockIdx.x == 0)
            for (long long j = (n4 << 2) + tid; j < n; j += TPB) PROC_I_LUT(ids[j]);
    }
#undef PROC_BIN
#undef PROC_F_AFF
#undef PROC_F_LUT
#undef PROC_I_AFF
#undef PROC_I_LUT

    __syncthreads();

    // ---- collapse replicas -> deterministic global partials ----
    for (int b = tid; b < n_local; b += TPB) {
        int s = 0;
#pragma unroll
        for (int r = 0; r < NWARPS; r++) s += s_hist[r][b];
        if (s) atomicAdd(&g_counts[b], s);
    }

    // ---- last-block finalize ----
    __threadfence();
    __shared__ unsigned s_rank;
    if (tid == 0) s_rank = atomicAdd(&g_done, 1u);
    __syncthreads();

    if (s_rank == NB - 1) {
        for (int b = tid; b < out_elems; b += TPB)
            out[b] = (b < n_local) ? (float)g_counts[b] : 0.0f;
        __syncthreads();
        for (int b = tid; b < MAX_BINS; b += TPB) g_counts[b] = 0;
        if (tid == 0) g_done = 0u;
    }
}

extern "C" void kernel_launch(void* const* d_in, const int* in_sizes, int n_in,
                              void* d_out, int out_size)
{
    int imax = 0;
    for (int i = 1; i < n_in; i++)
        if (in_sizes[i] > in_sizes[imax]) imax = i;

    const int* ids = (const int*)d_in[imax];
    long long n    = (long long)in_sizes[imax];

    const int* emap = nullptr;
    int map_n = 0;
    for (int i = 0; i < n_in; i++) {
        if (i == imax) continue;
        if (in_sizes[i] > 1 && in_sizes[i] <= MAX_MAP && in_sizes[i] > map_n) {
            emap  = (const int*)d_in[i];
            map_n = in_sizes[i];
        }
    }

    int n_local = out_size;
    if (n_local > MAX_BINS) n_local = MAX_BINS;
    if (n_local < 1) n_local = 1;

    hist_kernel<<<NB, TPB>>>(ids, n, emap, map_n, n_local,
                             (float*)d_out, out_size);
}

// round 12
// speedup vs baseline: 1.0020x; 1.0020x over previous
#include <cuda_runtime.h>
#include <cuda_bf16.h>

// MoE routing histogram, single fused kernel (float32 harness buffers).
//
// R12 vs R11: three structurally different kernels all plateau at 4.4TB/s
// with NO saturated pipe => classic multi-CTA wave spread (front-batched
// LDG.128, spr_max ~2.0 per B300 model; one-wave static partition makes the
// kernel as slow as its slowest CTA). Fix: DYNAMIC TILE SCHEDULER -- global
// ticket counter, 8192 tiles x 1024 int4, prefetched one tile ahead so the
// 318-cyc ATOMG latency hides under tile processing. Slow CTAs take fewer
// tiles; stragglers vanish.
// Retained: dtype sniff, binade fast path (no F2I), affine/LUT fallbacks,
// 8x per-warp replicated shared histograms, global-atomic partials,
// last-block finalize + full scratch re-zero (graph-replay safe).

#define NB        592      // 148 SMs * 4 CTAs
#define TPB       256
#define NWARPS    (TPB / 32)
#define MAX_BINS  256
#define BIN_PAD   (MAX_BINS + 1)
#define MAX_MAP   512
#define TUNROLL   4                      // int4 per thread per tile
#define TILE_I4   (TPB * TUNROLL)        // 1024 int4 = 16KB per tile

__device__ int g_counts[MAX_BINS];
__device__ unsigned g_done;
__device__ unsigned g_ticket;

__global__ __launch_bounds__(TPB, 4) void hist_kernel(
    const int* __restrict__ ids, long long n,
    const int* __restrict__ emap, int map_n, int n_local,
    float* __restrict__ out, int out_elems)
{
    __shared__ int s_map[MAX_MAP];
    __shared__ int s_hist[NWARPS][BIN_PAD];
    __shared__ int s_ids_int_ok, s_map_int_ok, s_affine, s_off;
    __shared__ unsigned s_tile[2];

    const int tid = threadIdx.x;

    // ---- dtype sniff ----
    if (tid == 0) { s_ids_int_ok = 1; s_map_int_ok = 1; s_affine = 1; s_off = 0x7FFFFFFF; }
    __syncthreads();
    if (tid < 256 && (long long)tid < n) {
        if ((unsigned)ids[tid] >= 65536u) atomicAnd(&s_ids_int_ok, 0);
    }
    if (emap != nullptr && tid < map_n) {
        unsigned w = (unsigned)emap[tid];
        if (w >= 65536u && w != 0xFFFFFFFFu) atomicAnd(&s_map_int_ok, 0);
    }
    __syncthreads();
    const int ids_float = !s_ids_int_ok;
    const int map_float = !s_map_int_ok;

    // ---- build LUT in int space ----
    int eff_map_n = map_n;
    if (emap != nullptr && map_n > 0) {
        if (map_float) {
            const float* mf = (const float*)emap;
            for (int i = tid; i < map_n; i += TPB) {
                float v = mf[i];
                s_map[i] = (v >= 0.0f && v < (float)MAX_BINS) ? (int)v : -1;
            }
        } else {
            for (int i = tid; i < map_n; i += TPB) s_map[i] = emap[i];
        }
    } else {
        eff_map_n = MAX_MAP;
        for (int i = tid; i < MAX_MAP; i += TPB) s_map[i] = (i < n_local) ? i : -1;
    }
    for (int i = tid; i < NWARPS * BIN_PAD; i += TPB) (&s_hist[0][0])[i] = 0;
    __syncthreads();

    // ---- affine detection ----
    const unsigned un = (unsigned)n_local;
    for (int i = tid; i < eff_map_n; i += TPB)
        if (s_map[i] >= 0) atomicMin(&s_off, i - s_map[i]);
    __syncthreads();
    const int off = s_off;
    for (int i = tid; i < eff_map_n; i += TPB) {
        int expect = ((unsigned)(i - off) < un) ? (i - off) : -1;
        if (s_map[i] != expect) atomicAnd(&s_affine, 0);
    }
    __syncthreads();
    const int affine = s_affine && (off != 0x7FFFFFFF) && (off >= 0) &&
                       (off + (int)un <= eff_map_n);

    // ---- binade fast-path constants ----
    int binade = 0; unsigned base_bits = 0, span = 0; int sh = 0;
    if (affine && ids_float && off > 0 && (int)un > 0) {
        int e_lo = 31 - __clz(off);
        int e_hi = 31 - __clz(off + (int)un - 1);
        if (e_lo == e_hi && e_lo <= 23) {
            binade    = 1;
            sh        = 23 - e_lo;
            base_bits = __float_as_uint((float)off);
            span      = un << sh;
        }
    }

    int* hist = s_hist[tid >> 5];
    const unsigned um = (unsigned)eff_map_n;
    const float off_f = (float)off;
    const long long st = (long long)NB * TPB;

#define PROC_BIN(W)                                                     \
    {                                                                   \
        unsigned _d = (unsigned)(W) - base_bits;                        \
        if (_d < span) atomicAdd(&hist[_d >> sh], 1);                   \
    }
#define PROC_F_AFF(W)                                                   \
    {                                                                   \
        int _m = (int)(__int_as_float(W) - off_f);                      \
        if ((unsigned)_m < un) atomicAdd(&hist[_m], 1);                 \
    }
#define PROC_F_LUT(W)                                                   \
    {                                                                   \
        unsigned _idx = (unsigned)(int)__int_as_float(W);               \
        int _m = (_idx < um) ? s_map[_idx] : -1;                        \
        if ((unsigned)_m < un) atomicAdd(&hist[_m], 1);                 \
    }
#define PROC_I_AFF(W)                                                   \
    {                                                                   \
        int _m = (W) - off;                                             \
        if ((unsigned)_m < un) atomicAdd(&hist[_m], 1);                 \
    }
#define PROC_I_LUT(W)                                                   \
    {                                                                   \
        unsigned _idx = (unsigned)(W);                                  \
        int _m = (_idx < um) ? s_map[_idx] : -1;                        \
        if ((unsigned)_m < un) atomicAdd(&hist[_m], 1);                 \
    }

    const int4* __restrict__ v = (const int4*)ids;
    const long long n4 = n >> 2;

    if (binade) {
        // ---- dynamic tile scheduler with one-ahead ticket prefetch ----
        const unsigned NT = (unsigned)(n4 / TILE_I4);
        if (tid == 0) s_tile[0] = atomicAdd(&g_ticket, 1u);
        __syncthreads();
        unsigned cur = s_tile[0];
        int p = 1;
        while (cur < NT) {
            if (tid == 0) s_tile[p] = atomicAdd(&g_ticket, 1u);  // prefetch next

            long long base = (long long)cur * TILE_I4 + tid;
            int4 v0 = __ldg(&v[base]);
            int4 v1 = __ldg(&v[base + TPB]);
            int4 v2 = __ldg(&v[base + 2 * TPB]);
            int4 v3 = __ldg(&v[base + 3 * TPB]);
            PROC_BIN(v0.x); PROC_BIN(v0.y); PROC_BIN(v0.z); PROC_BIN(v0.w);
            PROC_BIN(v1.x); PROC_BIN(v1.y); PROC_BIN(v1.z); PROC_BIN(v1.w);
            PROC_BIN(v2.x); PROC_BIN(v2.y); PROC_BIN(v2.z); PROC_BIN(v2.w);
            PROC_BIN(v3.x); PROC_BIN(v3.y); PROC_BIN(v3.z); PROC_BIN(v3.w);

            __syncthreads();           // s_tile[p] ready; everyone done with cur
            cur = s_tile[p];
            p ^= 1;
        }
        // remainder int4s + scalar tail: block 0
        if (blockIdx.x == 0) {
            for (long long i = (long long)NT * TILE_I4 + tid; i < n4; i += TPB) {
                int4 a = __ldg(&v[i]);
                PROC_BIN(a.x); PROC_BIN(a.y); PROC_BIN(a.z); PROC_BIN(a.w);
            }
            for (long long j = (n4 << 2) + tid; j < n; j += TPB) PROC_BIN(ids[j]);
        }
    } else if (ids_float && affine) {
        long long i = (long long)blockIdx.x * TPB + tid;
        for (; i + st < n4; i += 2 * st) {
            int4 va = __ldg(&v[i]);
            int4 vb = __ldg(&v[i + st]);
            PROC_F_AFF(va.x); PROC_F_AFF(va.y); PROC_F_AFF(va.z); PROC_F_AFF(va.w);
            PROC_F_AFF(vb.x); PROC_F_AFF(vb.y); PROC_F_AFF(vb.z); PROC_F_AFF(vb.w);
        }
        for (; i < n4; i += st) {
            int4 va = __ldg(&v[i]);
            PROC_F_AFF(va.x); PROC_F_AFF(va.y); PROC_F_AFF(va.z); PROC_F_AFF(va.w);
        }
        if (blockIdx.x == 0)
            for (long long j = (n4 << 2) + tid; j < n; j += TPB) PROC_F_AFF(ids[j]);
    } else if (ids_float) {
        long long i = (long long)blockIdx.x * TPB + tid;
        for (; i < n4; i += st) {
            int4 va = __ldg(&v[i]);
            PROC_F_LUT(va.x); PROC_F_LUT(va.y); PROC_F_LUT(va.z); PROC_F_LUT(va.w);
        }
        if (blockIdx.x == 0)
            for (long long j = (n4 << 2) + tid; j < n; j += TPB) PROC_F_LUT(ids[j]);
    } else if (affine) {
        long long i = (long long)blockIdx.x * TPB + tid;
        for (; i < n4; i += st) {
            int4 va = __ldg(&v[i]);
            PROC_I_AFF(va.x); PROC_I_AFF(va.y); PROC_I_AFF(va.z); PROC_I_AFF(va.w);
        }
        if (blockIdx.x == 0)
            for (long long j = (n4 << 2) + tid; j < n; j += TPB) PROC_I_AFF(ids[j]);
    } else {
        long long i = (long long)blockIdx.x * TPB + tid;
        for (; i < n4; i += st) {
            int4 va = __ldg(&v[i]);
            PROC_I_LUT(va.x); PROC_I_LUT(va.y); PROC_I_LUT(va.z); PROC_I_LUT(va.w);
        }
        if (blockIdx.x == 0)
            for (long long j = (n4 << 2) + tid; j < n; j += TPB) PROC_I_LUT(ids[j]);
    }
#undef PROC_BIN
#undef PROC_F_AFF
#undef PROC_F_LUT
#undef PROC_I_AFF
#undef PROC_I_LUT

    __syncthreads();

    // ---- collapse replicas -> deterministic global partials ----
    for (int b = tid; b < n_local; b += TPB) {
        int s = 0;
#pragma unroll
        for (int r = 0; r < NWARPS; r++) s += s_hist[r][b];
        if (s) atomicAdd(&g_counts[b], s);
    }

    // ---- last-block finalize (also resets ticket for the next replay) ----
    __threadfence();
    __shared__ unsigned s_rank;
    if (tid == 0) s_rank = atomicAdd(&g_done, 1u);
    __syncthreads();

    if (s_rank == NB - 1) {
        for (int b = tid; b < out_elems; b += TPB)
            out[b] = (b < n_local) ? (float)g_counts[b] : 0.0f;
        __syncthreads();
        for (int b = tid; b < MAX_BINS; b += TPB) g_counts[b] = 0;
        if (tid == 0) { g_done = 0u; g_ticket = 0u; }
    }
}

extern "C" void kernel_launch(void* const* d_in, const int* in_sizes, int n_in,
                              void* d_out, int out_size)
{
    int imax = 0;
    for (int i = 1; i < n_in; i++)
        if (in_sizes[i] > in_sizes[imax]) imax = i;

    const int* ids = (const int*)d_in[imax];
    long long n    = (long long)in_sizes[imax];

    const int* emap = nullptr;
    int map_n = 0;
    for (int i = 0; i < n_in; i++) {
        if (i == imax) continue;
        if (in_sizes[i] > 1 && in_sizes[i] <= MAX_MAP && in_sizes[i] > map_n) {
            emap  = (const int*)d_in[i];
            map_n = in_sizes[i];
        }
    }

    int n_local = out_size;
    if (n_local > MAX_BINS) n_local = MAX_BINS;
    if (n_local < 1) n_local = 1;

    hist_kernel<<<NB, TPB>>>(ids, n, emap, map_n, n_local,
                             (float*)d_out, out_size);
}